// round 16
// baseline (speedup 1.0000x reference)
#include <cuda_runtime.h>
#include <math.h>
#include <stdint.h>

#define BATCHN 8
#define NHEAD 12
#define BH 96            // BATCHN*NHEAD
#define SEQ 4096
#define HD 64
#define NL 64            // landmarks
#define SEG 64           // SEQ / NL
#define NSPLIT 8
#define SPLEN 512        // SEQ / NSPLIT
#define TS 64
#define NTF 8            // seq tiles per k_final block
#define SCALE 0.35355339059327373f   // 64^(-1/4)
#define NEGBIG 1000000000.0f
#define PA 68            // pitch for n-row-indexed mma buffers (== 4 mod 32, 16B rows)
#define PB 72            // pitch for k-row-indexed mma buffers (== 8 mod 32, 16B rows)
#define PI 65            // pitch for SIMT 64x64 matmuls (scalar access only!)
#define PT 68
#define P2 65

// -------- scratch --------
__device__ float g_Ql[BH*NL*HD];
__device__ float g_Kl[BH*NL*HD];
__device__ float g_K2[BH*NL*NL];
__device__ float g_colmax[BH];
__device__ float g_Inv[BH*NL*NL];
__device__ float g_pacc[BH*NSPLIT*NL*HD];
__device__ float g_pd[BH*NSPLIT*NL];
__device__ float g_W[BH*NL*HD];

__device__ __forceinline__ float tf32r(float x){
    uint32_t u; asm("cvt.rna.tf32.f32 %0, %1;" : "=r"(u) : "f"(x));
    return __uint_as_float(u);
}
__device__ __forceinline__ uint32_t tf32u(float x){
    uint32_t u; asm("cvt.rna.tf32.f32 %0, %1;" : "=r"(u) : "f"(x));
    return u;
}
__device__ __forceinline__ void mma8(float c[4],
                                     uint32_t a0,uint32_t a1,uint32_t a2,uint32_t a3,
                                     uint32_t b0,uint32_t b1){
    asm volatile("mma.sync.aligned.m16n8k8.row.col.f32.tf32.tf32.f32 "
        "{%0,%1,%2,%3}, {%4,%5,%6,%7}, {%8,%9}, {%0,%1,%2,%3};"
        : "+f"(c[0]),"+f"(c[1]),"+f"(c[2]),"+f"(c[3])
        : "r"(a0),"r"(a1),"r"(a2),"r"(a3),"r"(b0),"r"(b1));
}
__device__ __forceinline__ uint32_t smem_u32(const void* p){
    return (uint32_t)__cvta_generic_to_shared(p);
}
__device__ __forceinline__ void cpa16(uint32_t d, const void* s){
    asm volatile("cp.async.cg.shared.global [%0], [%1], 16;" :: "r"(d), "l"(s));
}
__device__ __forceinline__ void cp_commit(){ asm volatile("cp.async.commit_group;"); }
template<int N> __device__ __forceinline__ void cp_wait(){
    asm volatile("cp.async.wait_group %0;" :: "n"(N));
}
__device__ __forceinline__ void bar_pair(int id){
    asm volatile("bar.sync %0, 64;" :: "r"(id) : "memory");
}

// ================= dummy (shifts ncu's profiled launch slot onto k_mid) =========
__global__ void k_dummy(void) {}

// ================= K1: landmarks (float4, 16-deep MLP) =================
__global__ void __launch_bounds__(256) k_landmarks(const float* __restrict__ Q,
                                                   const float* __restrict__ K,
                                                   const float* __restrict__ mask) {
    int bh = blockIdx.y;
    int l  = blockIdx.x;
    int b  = bh / NHEAD;
    int t  = threadIdx.x;
    int c4 = (t & 15) << 2;
    int rg = t >> 4;                 // 16 row groups of 4 rows
    __shared__ float redQ[16][68];
    __shared__ float redK[16][68];
    const float* qb = Q + ((size_t)bh*SEQ + l*SEG)*HD;
    const float* kb = K + ((size_t)bh*SEQ + l*SEG)*HD;
    const float* mr = mask + (size_t)b*SEQ + l*SEG;
    float sq0=0.f,sq1=0.f,sq2=0.f,sq3=0.f;
    float sk0=0.f,sk1=0.f,sk2=0.f,sk3=0.f;
    #pragma unroll
    for (int k = 0; k < 4; k++) {
        int r = rg + k*16;
        float m = mr[r];
        float4 q = *(const float4*)(qb + r*HD + c4);
        float4 kk = *(const float4*)(kb + r*HD + c4);
        sq0 += q.x*m; sq1 += q.y*m; sq2 += q.z*m; sq3 += q.w*m;
        sk0 += kk.x*m; sk1 += kk.y*m; sk2 += kk.z*m; sk3 += kk.w*m;
    }
    *(float4*)&redQ[rg][c4] = make_float4(sq0,sq1,sq2,sq3);
    *(float4*)&redK[rg][c4] = make_float4(sk0,sk1,sk2,sk3);
    __syncthreads();
    if (t < NL) {
        float aq = 0.f, ak = 0.f;
        #pragma unroll
        for (int g = 0; g < 16; g++) { aq += redQ[g][t]; ak += redK[g][t]; }
        float cc = SCALE / (float)SEG;
        g_Ql[(bh*NL + l)*HD + t] = aq * cc;
        g_Kl[(bh*NL + l)*HD + t] = ak * cc;
    }
}

// ================= K2a: kernel_2 softmax + colsum max =================
__global__ void k_kernel2(void) {
    int bh = blockIdx.x;
    int t  = threadIdx.x;   // 64 threads
    __shared__ float sQ[NL*P2];
    __shared__ float sK[NL*P2];
    __shared__ float sP[NL*P2];
    __shared__ float red[NL];
    for (int r = 0; r < NL; r++) {
        sQ[r*P2 + t] = g_Ql[(bh*NL + r)*HD + t];
        sK[r*P2 + t] = g_Kl[(bh*NL + r)*HD + t];
    }
    __syncthreads();
    int l = t;
    float mx = -1e30f;
    for (int m = 0; m < NL; m++) {
        float s = 0.f;
        #pragma unroll 8
        for (int k = 0; k < HD; k++) s += sQ[l*P2 + k] * sK[m*P2 + k];
        sP[l*P2 + m] = s;
        mx = fmaxf(mx, s);
    }
    float sum = 0.f;
    for (int m = 0; m < NL; m++) {
        float e = __expf(sP[l*P2 + m] - mx);
        sP[l*P2 + m] = e;
        sum += e;
    }
    float inv = 1.f / sum;
    for (int m = 0; m < NL; m++) {
        float v = sP[l*P2 + m] * inv;
        sP[l*P2 + m] = v;
        g_K2[(bh*NL + l)*NL + m] = v;
    }
    __syncthreads();
    float cs = 0.f;
    for (int r = 0; r < NL; r++) cs += sP[r*P2 + t];
    red[t] = cs;
    __syncthreads();
    for (int s = 32; s > 0; s >>= 1) {
        if (t < s) red[t] = fmaxf(red[t], red[t + s]);
        __syncthreads();
    }
    if (t == 0) g_colmax[bh] = red[0];
}

// ===== 64x64 SIMT matmul: C = alpha * A @ (beta*I + gamma*B); C may alias A or B =====
template<int P>
__device__ __forceinline__ void mm64(float* C, const float* A, const float* B,
                                     float beta, float gamma, float alpha, int tid) {
    int i0 = (tid >> 4) << 2;
    int j0 = (tid & 15) << 2;
    float acc[4][4];
    #pragma unroll
    for (int u = 0; u < 4; u++)
        #pragma unroll
        for (int v = 0; v < 4; v++) acc[u][v] = 0.f;
    for (int k = 0; k < HD; k++) {
        float a[4], b[4];
        #pragma unroll
        for (int u = 0; u < 4; u++) a[u] = A[(i0+u)*P + k];
        #pragma unroll
        for (int v = 0; v < 4; v++) {
            float x = B[k*P + j0 + v];
            b[v] = gamma * x + ((k == j0 + v) ? beta : 0.f);
        }
        #pragma unroll
        for (int u = 0; u < 4; u++)
            #pragma unroll
            for (int v = 0; v < 4; v++) acc[u][v] += a[u] * b[v];
    }
    __syncthreads();
    #pragma unroll
    for (int u = 0; u < 4; u++)
        #pragma unroll
        for (int v = 0; v < 4; v++) C[(i0+u)*P + j0 + v] = alpha * acc[u][v];
    __syncthreads();
}

// ================= Newton-Schulz pinv body (fp32 SIMT, 4 buffers) =================
__device__ void inv_body(float* sm) {
    float* Km = sm;
    float* Vb = sm + 1*NL*PI;
    float* Pb = sm + 2*NL*PI;
    float* T1 = sm + 3*NL*PI;
    int bh = blockIdx.y;
    int tid = threadIdx.x;
    for (int e = tid; e < NL*NL; e += 256) {
        int r = e >> 6, c = e & 63;
        Km[r*PI + c] = g_K2[bh*NL*NL + e];
    }
    float gmax = -1e30f;
    for (int i = 0; i < BH; i++) gmax = fmaxf(gmax, g_colmax[i]);
    float ig = 1.f / gmax;
    __syncthreads();
    for (int e = tid; e < NL*NL; e += 256) {
        int r = e >> 6, c = e & 63;
        Vb[r*PI + c] = Km[c*PI + r] * ig;
    }
    __syncthreads();
    float *Vp = Vb, *Tp = T1;
    for (int it = 0; it < 6; it++) {
        mm64<PI>(Pb, Km, Vp, 0.f,  1.f, 1.f,   tid);
        mm64<PI>(Tp, Pb, Pb, 7.f, -1.f, 1.f,   tid);
        mm64<PI>(Pb, Pb, Tp, 15.f,-1.f, 1.f,   tid);
        mm64<PI>(Tp, Vp, Pb, 13.f,-1.f, 0.25f, tid);
        float* t = Vp; Vp = Tp; Tp = t;
    }
    for (int e = tid; e < NL*NL; e += 256) {
        int r = e >> 6, c = e & 63;
        g_Inv[bh*NL*NL + e] = Vp[r*PI + c];
    }
}

// ====== flash3 prefetch: raw K/V tiles + mask tile via cp.async ======
__device__ __forceinline__ void f3_prefetch(const float* K, const float* V,
                                            const float* mask, float* sKb, float* sVb,
                                            float* smaskb, int bh, int b, int s0, int tid){
    const float* Kb = K + ((size_t)bh*SEQ + s0)*HD;
    const float* Vb = V + ((size_t)bh*SEQ + s0)*HD;
    #pragma unroll
    for (int i = 0; i < 4; i++) {
        int e4 = tid + i*256;
        int r = e4 >> 4, c = (e4 & 15) << 2;
        cpa16(smem_u32(&sKb[r*PA + c]), Kb + r*HD + c);
        cpa16(smem_u32(&sVb[r*PB + c]), Vb + r*HD + c);
    }
    if (tid < 16) cpa16(smem_u32(&smaskb[tid*4]), mask + (size_t)b*SEQ + s0 + tid*4);
}

// ====== flash kernel_3 @ V body: Q fragments in regs, pair-barrier P exchange ======
__device__ void flash3_body(const float* __restrict__ K, const float* __restrict__ V,
                            const float* __restrict__ mask, float* sm) {
    float* sP  = sm;                      // 64 x PA  (Q staging, then P buffer)
    float* sK0 = sm + NL*PA;              // 64 x PA  raw K tiles
    float* sK1 = sm + 2*NL*PA;
    float* sV0 = sm + 3*NL*PA;            // 64 x PB  raw V tiles
    float* sV1 = sm + 3*NL*PA + NL*PB;
    __shared__ float smask[2][TS];
    __shared__ float dred[NL][2];

    int bh = blockIdx.y, sp = blockIdx.x, b = bh / NHEAD;
    int tid = threadIdx.x, lane = tid & 31, warp = tid >> 5;
    int wr = warp & 3, wc = warp >> 2;
    int g = lane >> 2, t4 = lane & 3;
    int r0 = wr*16 + g, r1 = r0 + 8;

    // prefetch tiles 0,1
    f3_prefetch(K, V, mask, sK0, sV0, smask[0], bh, b, sp*SPLEN + 0*TS, tid); cp_commit();
    f3_prefetch(K, V, mask, sK1, sV1, smask[1], bh, b, sp*SPLEN + 1*TS, tid); cp_commit();

    // stage rna(Ql*SCALE) into sP, pull A-fragments into registers, then recycle sP as P
    for (int e4 = tid; e4 < NL*HD/4; e4 += 256) {
        int r = e4 >> 4, c = (e4 & 15) << 2;
        float4 q = *(const float4*)&g_Ql[(size_t)bh*NL*HD + r*HD + c];
        *(float4*)&sP[r*PA + c] = make_float4(tf32r(q.x*SCALE), tf32r(q.y*SCALE),
                                              tf32r(q.z*SCALE), tf32r(q.w*SCALE));
    }
    __syncthreads();
    uint32_t qa[8][4];
    #pragma unroll
    for (int ks = 0; ks < 8; ks++) {
        int kb = ks*8 + t4;
        qa[ks][0] = __float_as_uint(sP[r0*PA + kb]);
        qa[ks][1] = __float_as_uint(sP[r1*PA + kb]);
        qa[ks][2] = __float_as_uint(sP[r0*PA + kb + 4]);
        qa[ks][3] = __float_as_uint(sP[r1*PA + kb + 4]);
    }

    float o[4][4];
    #pragma unroll
    for (int nt = 0; nt < 4; nt++)
        #pragma unroll
        for (int j = 0; j < 4; j++) o[nt][j] = 0.f;
    float dp0 = 0.f, dp1 = 0.f;

    for (int tt = 0; tt < SPLEN/TS; tt++) {
        int buf = tt & 1;
        float* sK = buf ? sK1 : sK0;
        float* sV = buf ? sV1 : sV0;
        cp_wait<1>();
        __syncthreads();   // K/V/mask tile ready; prior-tile P@V reads done

        // S = Ql @ Ks^T  per n-tile (cf[4] live), exp + stage P immediately
        #pragma unroll
        for (int nt = 0; nt < 4; nt++) {
            float cf[4] = {0.f, 0.f, 0.f, 0.f};
            int n = wc*32 + nt*8 + g;
            #pragma unroll
            for (int ks = 0; ks < 8; ks++) {
                int kb = ks*8 + t4;
                uint32_t b0 = tf32u(sK[n*PA + kb]);
                uint32_t b1 = tf32u(sK[n*PA + kb + 4]);
                mma8(cf, qa[ks][0], qa[ks][1], qa[ks][2], qa[ks][3], b0, b1);
            }
            int cb = wc*32 + nt*8 + t4*2;
            float bb0 = -NEGBIG * (1.f - smask[buf][cb]);
            float bb1 = -NEGBIG * (1.f - smask[buf][cb+1]);
            float e0 = __expf(cf[0] + bb0), e1 = __expf(cf[1] + bb1);
            float e2 = __expf(cf[2] + bb0), e3 = __expf(cf[3] + bb1);
            dp0 += e0 + e1; dp1 += e2 + e3;
            *(float2*)&sP[r0*PA + cb] = make_float2(tf32r(e0), tf32r(e1));
            *(float2*)&sP[r1*PA + cb] = make_float2(tf32r(e2), tf32r(e3));
        }
        bar_pair(wr + 1);   // pair-only: this band's P complete (wc halves)

        // O += P @ V
        #pragma unroll
        for (int ks = 0; ks < 8; ks++) {
            int kb = ks*8 + t4;
            uint32_t a0 = __float_as_uint(sP[r0*PA + kb]);
            uint32_t a1 = __float_as_uint(sP[r1*PA + kb]);
            uint32_t a2 = __float_as_uint(sP[r0*PA + kb + 4]);
            uint32_t a3 = __float_as_uint(sP[r1*PA + kb + 4]);
            #pragma unroll
            for (int nt = 0; nt < 4; nt++) {
                int n = wc*32 + nt*8 + g;
                uint32_t b0 = tf32u(sV[kb*PB + n]);
                uint32_t b1 = tf32u(sV[(kb+4)*PB + n]);
                mma8(o[nt], a0, a1, a2, a3, b0, b1);
            }
        }
        __syncthreads();   // all K/V reads done before overwrite
        if (tt + 2 < SPLEN/TS) {
            f3_prefetch(K, V, mask, sK, sV, smask[buf], bh, b,
                        sp*SPLEN + (tt+2)*TS, tid);
            cp_commit();
        }
    }
    size_t base = ((size_t)bh*NSPLIT + sp)*NL;
    #pragma unroll
    for (int nt = 0; nt < 4; nt++) {
        int cb = wc*32 + nt*8 + t4*2;
        *(float2*)&g_pacc[(base + r0)*HD + cb] = make_float2(o[nt][0], o[nt][1]);
        *(float2*)&g_pacc[(base + r1)*HD + cb] = make_float2(o[nt][2], o[nt][3]);
    }
    dp0 += __shfl_xor_sync(0xffffffffu, dp0, 1);
    dp0 += __shfl_xor_sync(0xffffffffu, dp0, 2);
    dp1 += __shfl_xor_sync(0xffffffffu, dp1, 1);
    dp1 += __shfl_xor_sync(0xffffffffu, dp1, 2);
    if (t4 == 0) { dred[r0][wc] = dp0; dred[r1][wc] = dp1; }
    __syncthreads();
    if (tid < NL) g_pd[base + tid] = dred[tid][0] + dred[tid][1];
}

// ================= fused middle kernel: flash3 (x<8) || inv (x==8) =================
__global__ void __launch_bounds__(256, 2) k_mid(const float* __restrict__ K,
                                                const float* __restrict__ V,
                                                const float* __restrict__ mask) {
    extern __shared__ float sm[];
    if (blockIdx.x < NSPLIT) flash3_body(K, V, mask, sm);
    else                     inv_body(sm);
}

// ================= merge partials + W = Inv @ T3V =================
__global__ void __launch_bounds__(256) k_mergewmat(void) {
    __shared__ float A[NL*PI];
    __shared__ float T[NL*PT];
    __shared__ float dtot[NL];
    int bh = blockIdx.x, tid = threadIdx.x;
    for (int e = tid; e < NL*NL; e += 256) {
        int r = e >> 6, c = e & 63;
        A[r*PI + c] = g_Inv[bh*NL*NL + e];
    }
    if (tid < NL) {
        float s = 0.f;
        #pragma unroll
        for (int k = 0; k < NSPLIT; k++) s += g_pd[((size_t)bh*NSPLIT + k)*NL + tid];
        dtot[tid] = s;
    }
    __syncthreads();
    for (int e4 = tid; e4 < NL*HD/4; e4 += 256) {
        int r = e4 >> 4, c = (e4 & 15) << 2;
        float4 acc = make_float4(0.f, 0.f, 0.f, 0.f);
        #pragma unroll
        for (int s = 0; s < NSPLIT; s++) {
            float4 p = *(const float4*)&g_pacc[(((size_t)bh*NSPLIT + s)*NL + r)*HD + c];
            acc.x += p.x; acc.y += p.y; acc.z += p.z; acc.w += p.w;
        }
        float id = 1.f / dtot[r];
        *(float4*)&T[r*PT + c] = make_float4(acc.x*id, acc.y*id, acc.z*id, acc.w*id);
    }
    __syncthreads();
    int i0 = (tid >> 4) << 2;
    int j0 = (tid & 15) << 2;
    float acc[4][4];
    #pragma unroll
    for (int u = 0; u < 4; u++)
        #pragma unroll
        for (int v = 0; v < 4; v++) acc[u][v] = 0.f;
    for (int k = 0; k < NL; k++) {
        float a[4], b[4];
        #pragma unroll
        for (int u = 0; u < 4; u++) a[u] = A[(i0+u)*PI + k];
        #pragma unroll
        for (int v = 0; v < 4; v++) b[v] = T[k*PT + j0 + v];
        #pragma unroll
        for (int u = 0; u < 4; u++)
            #pragma unroll
            for (int v = 0; v < 4; v++) acc[u][v] += a[u] * b[v];
    }
    #pragma unroll
    for (int u = 0; u < 4; u++)
        #pragma unroll
        for (int v = 0; v < 4; v++)
            g_W[((size_t)bh*NL + i0 + u)*HD + j0 + v] = acc[u][v];
}

// ===== K5: X = softmax(Qs K_l^T) @ W — 3 blocks/SM, sP aliased onto consumed sQ =====
__global__ void __launch_bounds__(256, 3) k_final(const float* __restrict__ Q,
                                                  const float* __restrict__ mask,
                                                  float* __restrict__ out) {
    extern __shared__ float sm[];
    float* sKl = sm;                     // 64 x PA  (rounded at staging)
    float* sQ0 = sm + NL*PA;             // 64 x PA  raw Q / then P (band-aliased)
    float* sQ1 = sm + 2*NL*PA;
    float* sW  = sm + 3*NL*PA;           // 64 x PB  (rounded at staging)
    __shared__ float smk[2][TS];
    __shared__ float rsum[NL][2];

    int bh = blockIdx.y, b = bh / NHEAD;
    int tid = threadIdx.x, lane = tid & 31, warp = tid >> 5;
    int wr = warp & 3, wc = warp >> 2;
    int g = lane >> 2, t4 = lane & 3;
    int r0 = wr*16 + g, r1 = r0 + 8;

    // prefetch Q tiles 0,1 (raw) + mask
    #pragma unroll
    for (int p = 0; p < 2; p++) {
        int s0 = (blockIdx.x*NTF + p)*TS;
        const float* Qb = Q + ((size_t)bh*SEQ + s0)*HD;
        float* dst = p ? sQ1 : sQ0;
        #pragma unroll
        for (int i = 0; i < 4; i++) {
            int e4 = tid + i*256;
            int r = e4 >> 4, c = (e4 & 15) << 2;
            cpa16(smem_u32(&dst[r*PA + c]), Qb + r*HD + c);
        }
        if (tid < 16) cpa16(smem_u32(&smk[p][tid*4]), mask + (size_t)b*SEQ + s0 + tid*4);
        cp_commit();
    }

    for (int e4 = tid; e4 < NL*HD/4; e4 += 256) {
        int r = e4 >> 4, c = (e4 & 15) << 2;
        float4 kl = *(const float4*)&g_Kl[(size_t)bh*NL*HD + r*HD + c];
        float4 w  = *(const float4*)&g_W[(size_t)bh*NL*HD + r*HD + c];
        *(float4*)&sKl[r*PA + c] = make_float4(tf32r(kl.x), tf32r(kl.y), tf32r(kl.z), tf32r(kl.w));
        *(float4*)&sW[r*PB + c]  = make_float4(tf32r(w.x), tf32r(w.y), tf32r(w.z), tf32r(w.w));
    }

    for (int tt = 0; tt < NTF; tt++) {
        int buf = tt & 1;
        float* sQ = buf ? sQ1 : sQ0;     // raw Q tile; becomes P after pair barrier
        cp_wait<1>();
        __syncthreads();                  // Q tile ready (+ sKl/sW on tt=0)

        // pull this band's Q fragments (RNA-rounded) into regs, then free the band for P
        uint32_t qa[8][4];
        #pragma unroll
        for (int ks = 0; ks < 8; ks++) {
            int kb = ks*8 + t4;
            qa[ks][0] = tf32u(sQ[r0*PA + kb]);
            qa[ks][1] = tf32u(sQ[r1*PA + kb]);
            qa[ks][2] = tf32u(sQ[r0*PA + kb + 4]);
            qa[ks][3] = tf32u(sQ[r1*PA + kb + 4]);
        }
        bar_pair(wr + 1);                 // pair done reading its Q band

        float f0 = smk[buf][r0] * SCALE;
        float f1 = smk[buf][r1] * SCALE;
        float dp0 = 0.f, dp1 = 0.f;
        #pragma unroll
        for (int nt = 0; nt < 4; nt++) {
            float cf[4] = {0.f, 0.f, 0.f, 0.f};
            int n = wc*32 + nt*8 + g;
            #pragma unroll
            for (int ks = 0; ks < 8; ks++) {
                int kb = ks*8 + t4;
                uint32_t b0 = __float_as_uint(sKl[n*PA + kb]);
                uint32_t b1 = __float_as_uint(sKl[n*PA + kb + 4]);
                mma8(cf, qa[ks][0], qa[ks][1], qa[ks][2], qa[ks][3], b0, b1);
            }
            int cb = wc*32 + nt*8 + t4*2;
            float e0 = __expf(cf[0]*f0), e1 = __expf(cf[1]*f0);
            float e2 = __expf(cf[2]*f1), e3 = __expf(cf[3]*f1);
            dp0 += e0 + e1; dp1 += e2 + e3;
            *(float2*)&sQ[r0*PA + cb] = make_float2(tf32r(e0), tf32r(e1));
            *(float2*)&sQ[r1*PA + cb] = make_float2(tf32r(e2), tf32r(e3));
        }
        dp0 += __shfl_xor_sync(0xffffffffu, dp0, 1);
        dp0 += __shfl_xor_sync(0xffffffffu, dp0, 2);
        dp1 += __shfl_xor_sync(0xffffffffu, dp1, 1);
        dp1 += __shfl_xor_sync(0xffffffffu, dp1, 2);
        if (t4 == 0) { rsum[r0][wc] = dp0; rsum[r1][wc] = dp1; }
        bar_pair(wr + 1);                 // pair: P band + rsum visible

        float o[4][4];
        #pragma unroll
        for (int nt = 0; nt < 4; nt++)
            #pragma unroll
            for (int j = 0; j < 4; j++) o[nt][j] = 0.f;
        #pragma unroll
        for (int ks = 0; ks < 8; ks++) {
            int kb = ks*8 + t4;
            uint32_t a0 = __float_as_uint(sQ[r0*PA + kb]);
            uint32_t a1 = __float_as_uint(sQ[r1*PA + kb]);
            uint32_t a2 = __float_as_uint(sQ[r0*PA + kb + 4]);
            uint32_t a3 = __float_as_uint(sQ[r1*PA + kb + 4]);
            #pragma unroll
            for (int nt = 0; nt < 4; nt++) {
                int n = wc*32 + nt*8 + g;
                uint32_t b0 = __float_as_uint(sW[kb*PB + n]);
                uint32_t b1 = __float_as_uint(sW[(kb+4)*PB + n]);
                mma8(o[nt], a0, a1, a2, a3, b0, b1);
            }
        }
        int s0 = (blockIdx.x*NTF + tt)*TS;
        float ri0 = 1.f / (rsum[r0][0] + rsum[r0][1]);
        float ri1 = 1.f / (rsum[r1][0] + rsum[r1][1]);
        #pragma unroll
        for (int nt = 0; nt < 4; nt++) {
            int cb = wc*32 + nt*8 + t4*2;
            *(float2*)&out[((size_t)bh*SEQ + s0 + r0)*HD + cb] =
                make_float2(o[nt][0]*ri0, o[nt][1]*ri0);
            *(float2*)&out[((size_t)bh*SEQ + s0 + r1)*HD + cb] =
                make_float2(o[nt][2]*ri1, o[nt][3]*ri1);
        }
        __syncthreads();                  // all bands' P reads done before overwrite
        if (tt + 2 < NTF) {
            int sn = (blockIdx.x*NTF + tt + 2)*TS;
            const float* Qb = Q + ((size_t)bh*SEQ + sn)*HD;
            #pragma unroll
            for (int i = 0; i < 4; i++) {
                int e4 = tid + i*256;
                int r = e4 >> 4, c = (e4 & 15) << 2;
                cpa16(smem_u32(&sQ[r*PA + c]), Qb + r*HD + c);
            }
            if (tid < 16) cpa16(smem_u32(&smk[buf][tid*4]),
                                mask + (size_t)b*SEQ + sn + tid*4);
            cp_commit();
        }
    }
}

// ================= launch =================
extern "C" void kernel_launch(void* const* d_in, const int* in_sizes, int n_in,
                              void* d_out, int out_size) {
    const float* Q    = (const float*)d_in[0];
    const float* K    = (const float*)d_in[1];
    const float* V    = (const float*)d_in[2];
    const float* mask = (const float*)d_in[3];
    float* out = (float*)d_out;

    const int SMEM_MID = (3 * NL * PA + 2 * NL * PB) * sizeof(float);  // 89088
    const int SMEM_FIN = (3 * NL * PA + NL * PB) * sizeof(float);      // 70656
    cudaFuncSetAttribute(k_mid,   cudaFuncAttributeMaxDynamicSharedMemorySize, SMEM_MID);
    cudaFuncSetAttribute(k_final, cudaFuncAttributeMaxDynamicSharedMemorySize, SMEM_FIN);

    k_landmarks<<<dim3(NL, BH), 256>>>(Q, K, mask);     // launch 0
    k_kernel2<<<BH, NL>>>();                            // launch 1
    k_dummy<<<1, 32>>>();                               // launch 2 (slot shim)
    k_mid<<<dim3(NSPLIT + 1, BH), 256, SMEM_MID>>>(K, V, mask);  // launch 3 <- profiled
    k_mergewmat<<<BH, 256>>>();                         // launch 4
    k_final<<<dim3(SEQ/TS/NTF, BH), 256, SMEM_FIN>>>(Q, mask, out);  // launch 5
}

// round 17
// speedup vs baseline: 1.0009x; 1.0009x over previous
#include <cuda_runtime.h>
#include <math.h>
#include <stdint.h>

#define BATCHN 8
#define NHEAD 12
#define BH 96            // BATCHN*NHEAD
#define SEQ 4096
#define HD 64
#define NL 64            // landmarks
#define SEG 64           // SEQ / NL
#define NSPLIT 8
#define SPLEN 512        // SEQ / NSPLIT
#define TS 64
#define NTF 8            // seq tiles per k_final block
#define SCALE 0.35355339059327373f   // 64^(-1/4)
#define NEGBIG 1000000000.0f
#define PA 68            // pitch for n-row-indexed mma buffers (== 4 mod 32, 16B rows)
#define PB 72            // pitch for k-row-indexed mma buffers (== 8 mod 32, 16B rows)
#define PI 65            // pitch for SIMT 64x64 matmuls (scalar access only!)
#define PT 68
#define P2 65

// -------- scratch --------
__device__ float g_Ql[BH*NL*HD];
__device__ float g_Kl[BH*NL*HD];
__device__ float g_K2[BH*NL*NL];
__device__ float g_colmax[BH];
__device__ float g_Inv[BH*NL*NL];
__device__ float g_pacc[BH*NSPLIT*NL*HD];
__device__ float g_pd[BH*NSPLIT*NL];
__device__ float g_W[BH*NL*HD];

__device__ __forceinline__ float tf32r(float x){
    uint32_t u; asm("cvt.rna.tf32.f32 %0, %1;" : "=r"(u) : "f"(x));
    return __uint_as_float(u);
}
__device__ __forceinline__ uint32_t tf32u(float x){
    uint32_t u; asm("cvt.rna.tf32.f32 %0, %1;" : "=r"(u) : "f"(x));
    return u;
}
__device__ __forceinline__ void mma8(float c[4],
                                     uint32_t a0,uint32_t a1,uint32_t a2,uint32_t a3,
                                     uint32_t b0,uint32_t b1){
    asm volatile("mma.sync.aligned.m16n8k8.row.col.f32.tf32.tf32.f32 "
        "{%0,%1,%2,%3}, {%4,%5,%6,%7}, {%8,%9}, {%0,%1,%2,%3};"
        : "+f"(c[0]),"+f"(c[1]),"+f"(c[2]),"+f"(c[3])
        : "r"(a0),"r"(a1),"r"(a2),"r"(a3),"r"(b0),"r"(b1));
}
__device__ __forceinline__ uint32_t smem_u32(const void* p){
    return (uint32_t)__cvta_generic_to_shared(p);
}
__device__ __forceinline__ void cpa16(uint32_t d, const void* s){
    asm volatile("cp.async.cg.shared.global [%0], [%1], 16;" :: "r"(d), "l"(s));
}
__device__ __forceinline__ void cp_commit(){ asm volatile("cp.async.commit_group;"); }
template<int N> __device__ __forceinline__ void cp_wait(){
    asm volatile("cp.async.wait_group %0;" :: "n"(N));
}
__device__ __forceinline__ void bar_pair(int id){
    asm volatile("bar.sync %0, 64;" :: "r"(id) : "memory");
}

// ================= dummy (shifts ncu's profiled launch slot onto k_mid) =========
__global__ void k_dummy(void) {}

// ================= K1: landmarks (float4, 16-deep MLP) =================
__global__ void __launch_bounds__(256) k_landmarks(const float* __restrict__ Q,
                                                   const float* __restrict__ K,
                                                   const float* __restrict__ mask) {
    int bh = blockIdx.y;
    int l  = blockIdx.x;
    int b  = bh / NHEAD;
    int t  = threadIdx.x;
    int c4 = (t & 15) << 2;
    int rg = t >> 4;                 // 16 row groups of 4 rows
    __shared__ float redQ[16][68];
    __shared__ float redK[16][68];
    const float* qb = Q + ((size_t)bh*SEQ + l*SEG)*HD;
    const float* kb = K + ((size_t)bh*SEQ + l*SEG)*HD;
    const float* mr = mask + (size_t)b*SEQ + l*SEG;
    float sq0=0.f,sq1=0.f,sq2=0.f,sq3=0.f;
    float sk0=0.f,sk1=0.f,sk2=0.f,sk3=0.f;
    #pragma unroll
    for (int k = 0; k < 4; k++) {
        int r = rg + k*16;
        float m = mr[r];
        float4 q = *(const float4*)(qb + r*HD + c4);
        float4 kk = *(const float4*)(kb + r*HD + c4);
        sq0 += q.x*m; sq1 += q.y*m; sq2 += q.z*m; sq3 += q.w*m;
        sk0 += kk.x*m; sk1 += kk.y*m; sk2 += kk.z*m; sk3 += kk.w*m;
    }
    *(float4*)&redQ[rg][c4] = make_float4(sq0,sq1,sq2,sq3);
    *(float4*)&redK[rg][c4] = make_float4(sk0,sk1,sk2,sk3);
    __syncthreads();
    if (t < NL) {
        float aq = 0.f, ak = 0.f;
        #pragma unroll
        for (int g = 0; g < 16; g++) { aq += redQ[g][t]; ak += redK[g][t]; }
        float cc = SCALE / (float)SEG;
        g_Ql[(bh*NL + l)*HD + t] = aq * cc;
        g_Kl[(bh*NL + l)*HD + t] = ak * cc;
    }
}

// ================= K2a: kernel_2 softmax + colsum max =================
__global__ void k_kernel2(void) {
    int bh = blockIdx.x;
    int t  = threadIdx.x;   // 64 threads
    __shared__ float sQ[NL*P2];
    __shared__ float sK[NL*P2];
    __shared__ float sP[NL*P2];
    __shared__ float red[NL];
    for (int r = 0; r < NL; r++) {
        sQ[r*P2 + t] = g_Ql[(bh*NL + r)*HD + t];
        sK[r*P2 + t] = g_Kl[(bh*NL + r)*HD + t];
    }
    __syncthreads();
    int l = t;
    float mx = -1e30f;
    for (int m = 0; m < NL; m++) {
        float s = 0.f;
        #pragma unroll 8
        for (int k = 0; k < HD; k++) s += sQ[l*P2 + k] * sK[m*P2 + k];
        sP[l*P2 + m] = s;
        mx = fmaxf(mx, s);
    }
    float sum = 0.f;
    for (int m = 0; m < NL; m++) {
        float e = __expf(sP[l*P2 + m] - mx);
        sP[l*P2 + m] = e;
        sum += e;
    }
    float inv = 1.f / sum;
    for (int m = 0; m < NL; m++) {
        float v = sP[l*P2 + m] * inv;
        sP[l*P2 + m] = v;
        g_K2[(bh*NL + l)*NL + m] = v;
    }
    __syncthreads();
    float cs = 0.f;
    for (int r = 0; r < NL; r++) cs += sP[r*P2 + t];
    red[t] = cs;
    __syncthreads();
    for (int s = 32; s > 0; s >>= 1) {
        if (t < s) red[t] = fmaxf(red[t], red[t + s]);
        __syncthreads();
    }
    if (t == 0) g_colmax[bh] = red[0];
}

// ===== 64x64 SIMT matmul: C = alpha * A @ (beta*I + gamma*B); C may alias A or B =====
template<int P>
__device__ __forceinline__ void mm64(float* C, const float* A, const float* B,
                                     float beta, float gamma, float alpha, int tid) {
    int i0 = (tid >> 4) << 2;
    int j0 = (tid & 15) << 2;
    float acc[4][4];
    #pragma unroll
    for (int u = 0; u < 4; u++)
        #pragma unroll
        for (int v = 0; v < 4; v++) acc[u][v] = 0.f;
    for (int k = 0; k < HD; k++) {
        float a[4], b[4];
        #pragma unroll
        for (int u = 0; u < 4; u++) a[u] = A[(i0+u)*P + k];
        #pragma unroll
        for (int v = 0; v < 4; v++) {
            float x = B[k*P + j0 + v];
            b[v] = gamma * x + ((k == j0 + v) ? beta : 0.f);
        }
        #pragma unroll
        for (int u = 0; u < 4; u++)
            #pragma unroll
            for (int v = 0; v < 4; v++) acc[u][v] += a[u] * b[v];
    }
    __syncthreads();
    #pragma unroll
    for (int u = 0; u < 4; u++)
        #pragma unroll
        for (int v = 0; v < 4; v++) C[(i0+u)*P + j0 + v] = alpha * acc[u][v];
    __syncthreads();
}

// ================= Newton-Schulz pinv body (fp32 SIMT, 4 buffers) =================
__device__ void inv_body(float* sm) {
    float* Km = sm;
    float* Vb = sm + 1*NL*PI;
    float* Pb = sm + 2*NL*PI;
    float* T1 = sm + 3*NL*PI;
    int bh = blockIdx.y;
    int tid = threadIdx.x;
    for (int e = tid; e < NL*NL; e += 256) {
        int r = e >> 6, c = e & 63;
        Km[r*PI + c] = g_K2[bh*NL*NL + e];
    }
    float gmax = -1e30f;
    for (int i = 0; i < BH; i++) gmax = fmaxf(gmax, g_colmax[i]);
    float ig = 1.f / gmax;
    __syncthreads();
    for (int e = tid; e < NL*NL; e += 256) {
        int r = e >> 6, c = e & 63;
        Vb[r*PI + c] = Km[c*PI + r] * ig;
    }
    __syncthreads();
    float *Vp = Vb, *Tp = T1;
    for (int it = 0; it < 6; it++) {
        mm64<PI>(Pb, Km, Vp, 0.f,  1.f, 1.f,   tid);
        mm64<PI>(Tp, Pb, Pb, 7.f, -1.f, 1.f,   tid);
        mm64<PI>(Pb, Pb, Tp, 15.f,-1.f, 1.f,   tid);
        mm64<PI>(Tp, Vp, Pb, 13.f,-1.f, 0.25f, tid);
        float* t = Vp; Vp = Tp; Tp = t;
    }
    for (int e = tid; e < NL*NL; e += 256) {
        int r = e >> 6, c = e & 63;
        g_Inv[bh*NL*NL + e] = Vp[r*PI + c];
    }
}

// ====== flash3 prefetch: raw K/V tiles + mask tile via cp.async ======
__device__ __forceinline__ void f3_prefetch(const float* K, const float* V,
                                            const float* mask, float* sKb, float* sVb,
                                            float* smaskb, int bh, int b, int s0, int tid){
    const float* Kb = K + ((size_t)bh*SEQ + s0)*HD;
    const float* Vb = V + ((size_t)bh*SEQ + s0)*HD;
    #pragma unroll
    for (int i = 0; i < 4; i++) {
        int e4 = tid + i*256;
        int r = e4 >> 4, c = (e4 & 15) << 2;
        cpa16(smem_u32(&sKb[r*PA + c]), Kb + r*HD + c);
        cpa16(smem_u32(&sVb[r*PB + c]), Vb + r*HD + c);
    }
    if (tid < 16) cpa16(smem_u32(&smaskb[tid*4]), mask + (size_t)b*SEQ + s0 + tid*4);
}

// ====== flash kernel_3 @ V body: Q fragments in regs, pair-barrier P exchange ======
__device__ void flash3_body(const float* __restrict__ K, const float* __restrict__ V,
                            const float* __restrict__ mask, float* sm) {
    float* sP  = sm;                      // 64 x PA  (Q staging, then P buffer)
    float* sK0 = sm + NL*PA;              // 64 x PA  raw K tiles
    float* sK1 = sm + 2*NL*PA;
    float* sV0 = sm + 3*NL*PA;            // 64 x PB  raw V tiles
    float* sV1 = sm + 3*NL*PA + NL*PB;
    __shared__ float smask[2][TS];
    __shared__ float dred[NL][2];

    int bh = blockIdx.y, sp = blockIdx.x, b = bh / NHEAD;
    int tid = threadIdx.x, lane = tid & 31, warp = tid >> 5;
    int wr = warp & 3, wc = warp >> 2;
    int g = lane >> 2, t4 = lane & 3;
    int r0 = wr*16 + g, r1 = r0 + 8;

    // prefetch tiles 0,1
    f3_prefetch(K, V, mask, sK0, sV0, smask[0], bh, b, sp*SPLEN + 0*TS, tid); cp_commit();
    f3_prefetch(K, V, mask, sK1, sV1, smask[1], bh, b, sp*SPLEN + 1*TS, tid); cp_commit();

    // stage rna(Ql*SCALE) into sP, pull A-fragments into registers, then recycle sP as P
    for (int e4 = tid; e4 < NL*HD/4; e4 += 256) {
        int r = e4 >> 4, c = (e4 & 15) << 2;
        float4 q = *(const float4*)&g_Ql[(size_t)bh*NL*HD + r*HD + c];
        *(float4*)&sP[r*PA + c] = make_float4(tf32r(q.x*SCALE), tf32r(q.y*SCALE),
                                              tf32r(q.z*SCALE), tf32r(q.w*SCALE));
    }
    __syncthreads();
    uint32_t qa[8][4];
    #pragma unroll
    for (int ks = 0; ks < 8; ks++) {
        int kb = ks*8 + t4;
        qa[ks][0] = __float_as_uint(sP[r0*PA + kb]);
        qa[ks][1] = __float_as_uint(sP[r1*PA + kb]);
        qa[ks][2] = __float_as_uint(sP[r0*PA + kb + 4]);
        qa[ks][3] = __float_as_uint(sP[r1*PA + kb + 4]);
    }

    float o[4][4];
    #pragma unroll
    for (int nt = 0; nt < 4; nt++)
        #pragma unroll
        for (int j = 0; j < 4; j++) o[nt][j] = 0.f;
    float dp0 = 0.f, dp1 = 0.f;

    for (int tt = 0; tt < SPLEN/TS; tt++) {
        int buf = tt & 1;
        float* sK = buf ? sK1 : sK0;
        float* sV = buf ? sV1 : sV0;
        cp_wait<1>();
        __syncthreads();   // K/V/mask tile ready; prior-tile P@V reads done

        // S = Ql @ Ks^T  per n-tile (cf[4] live), exp + stage P immediately
        #pragma unroll
        for (int nt = 0; nt < 4; nt++) {
            float cf[4] = {0.f, 0.f, 0.f, 0.f};
            int n = wc*32 + nt*8 + g;
            #pragma unroll
            for (int ks = 0; ks < 8; ks++) {
                int kb = ks*8 + t4;
                uint32_t b0 = tf32u(sK[n*PA + kb]);
                uint32_t b1 = tf32u(sK[n*PA + kb + 4]);
                mma8(cf, qa[ks][0], qa[ks][1], qa[ks][2], qa[ks][3], b0, b1);
            }
            int cb = wc*32 + nt*8 + t4*2;
            float bb0 = -NEGBIG * (1.f - smask[buf][cb]);
            float bb1 = -NEGBIG * (1.f - smask[buf][cb+1]);
            float e0 = __expf(cf[0] + bb0), e1 = __expf(cf[1] + bb1);
            float e2 = __expf(cf[2] + bb0), e3 = __expf(cf[3] + bb1);
            dp0 += e0 + e1; dp1 += e2 + e3;
            *(float2*)&sP[r0*PA + cb] = make_float2(tf32r(e0), tf32r(e1));
            *(float2*)&sP[r1*PA + cb] = make_float2(tf32r(e2), tf32r(e3));
        }
        bar_pair(wr + 1);   // pair-only: this band's P complete (wc halves)

        // O += P @ V
        #pragma unroll
        for (int ks = 0; ks < 8; ks++) {
            int kb = ks*8 + t4;
            uint32_t a0 = __float_as_uint(sP[r0*PA + kb]);
            uint32_t a1 = __float_as_uint(sP[r1*PA + kb]);
            uint32_t a2 = __float_as_uint(sP[r0*PA + kb + 4]);
            uint32_t a3 = __float_as_uint(sP[r1*PA + kb + 4]);
            #pragma unroll
            for (int nt = 0; nt < 4; nt++) {
                int n = wc*32 + nt*8 + g;
                uint32_t b0 = tf32u(sV[kb*PB + n]);
                uint32_t b1 = tf32u(sV[(kb+4)*PB + n]);
                mma8(o[nt], a0, a1, a2, a3, b0, b1);
            }
        }
        __syncthreads();   // all K/V reads done before overwrite
        if (tt + 2 < SPLEN/TS) {
            f3_prefetch(K, V, mask, sK, sV, smask[buf], bh, b,
                        sp*SPLEN + (tt+2)*TS, tid);
            cp_commit();
        }
    }
    size_t base = ((size_t)bh*NSPLIT + sp)*NL;
    #pragma unroll
    for (int nt = 0; nt < 4; nt++) {
        int cb = wc*32 + nt*8 + t4*2;
        *(float2*)&g_pacc[(base + r0)*HD + cb] = make_float2(o[nt][0], o[nt][1]);
        *(float2*)&g_pacc[(base + r1)*HD + cb] = make_float2(o[nt][2], o[nt][3]);
    }
    dp0 += __shfl_xor_sync(0xffffffffu, dp0, 1);
    dp0 += __shfl_xor_sync(0xffffffffu, dp0, 2);
    dp1 += __shfl_xor_sync(0xffffffffu, dp1, 1);
    dp1 += __shfl_xor_sync(0xffffffffu, dp1, 2);
    if (t4 == 0) { dred[r0][wc] = dp0; dred[r1][wc] = dp1; }
    __syncthreads();
    if (tid < NL) g_pd[base + tid] = dred[tid][0] + dred[tid][1];
}

// ================= fused middle kernel: flash3 (x<8) || inv (x==8) =================
__global__ void __launch_bounds__(256, 2) k_mid(const float* __restrict__ K,
                                                const float* __restrict__ V,
                                                const float* __restrict__ mask) {
    extern __shared__ float sm[];
    if (blockIdx.x < NSPLIT) flash3_body(K, V, mask, sm);
    else                     inv_body(sm);
}

// ================= merge partials + W = Inv @ T3V =================
__global__ void __launch_bounds__(256) k_mergewmat(void) {
    __shared__ float A[NL*PI];
    __shared__ float T[NL*PT];
    __shared__ float dtot[NL];
    int bh = blockIdx.x, tid = threadIdx.x;
    for (int e = tid; e < NL*NL; e += 256) {
        int r = e >> 6, c = e & 63;
        A[r*PI + c] = g_Inv[bh*NL*NL + e];
    }
    if (tid < NL) {
        float s = 0.f;
        #pragma unroll
        for (int k = 0; k < NSPLIT; k++) s += g_pd[((size_t)bh*NSPLIT + k)*NL + tid];
        dtot[tid] = s;
    }
    __syncthreads();
    for (int e4 = tid; e4 < NL*HD/4; e4 += 256) {
        int r = e4 >> 4, c = (e4 & 15) << 2;
        float4 acc = make_float4(0.f, 0.f, 0.f, 0.f);
        #pragma unroll
        for (int s = 0; s < NSPLIT; s++) {
            float4 p = *(const float4*)&g_pacc[(((size_t)bh*NSPLIT + s)*NL + r)*HD + c];
            acc.x += p.x; acc.y += p.y; acc.z += p.z; acc.w += p.w;
        }
        float id = 1.f / dtot[r];
        *(float4*)&T[r*PT + c] = make_float4(acc.x*id, acc.y*id, acc.z*id, acc.w*id);
    }
    __syncthreads();
    int i0 = (tid >> 4) << 2;
    int j0 = (tid & 15) << 2;
    float acc[4][4];
    #pragma unroll
    for (int u = 0; u < 4; u++)
        #pragma unroll
        for (int v = 0; v < 4; v++) acc[u][v] = 0.f;
    for (int k = 0; k < NL; k++) {
        float a[4], b[4];
        #pragma unroll
        for (int u = 0; u < 4; u++) a[u] = A[(i0+u)*PI + k];
        #pragma unroll
        for (int v = 0; v < 4; v++) b[v] = T[k*PT + j0 + v];
        #pragma unroll
        for (int u = 0; u < 4; u++)
            #pragma unroll
            for (int v = 0; v < 4; v++) acc[u][v] += a[u] * b[v];
    }
    #pragma unroll
    for (int u = 0; u < 4; u++)
        #pragma unroll
        for (int v = 0; v < 4; v++)
            g_W[((size_t)bh*NL + i0 + u)*HD + j0 + v] = acc[u][v];
}

// ===== K5: X = softmax(Qs K_l^T) @ W — 3 blocks/SM, sP aliased onto consumed sQ =====
__global__ void __launch_bounds__(256, 3) k_final(const float* __restrict__ Q,
                                                  const float* __restrict__ mask,
                                                  float* __restrict__ out) {
    extern __shared__ float sm[];
    float* sKl = sm;                     // 64 x PA  (rounded at staging)
    float* sQ0 = sm + NL*PA;             // 64 x PA  raw Q / then P (band-aliased)
    float* sQ1 = sm + 2*NL*PA;
    float* sW  = sm + 3*NL*PA;           // 64 x PB  (rounded at staging)
    __shared__ float smk[2][TS];
    __shared__ float rsum[NL][2];

    int bh = blockIdx.y, b = bh / NHEAD;
    int tid = threadIdx.x, lane = tid & 31, warp = tid >> 5;
    int wr = warp & 3, wc = warp >> 2;
    int g = lane >> 2, t4 = lane & 3;
    int r0 = wr*16 + g, r1 = r0 + 8;

    // prefetch Q tiles 0,1 (raw) + mask
    #pragma unroll
    for (int p = 0; p < 2; p++) {
        int s0 = (blockIdx.x*NTF + p)*TS;
        const float* Qb = Q + ((size_t)bh*SEQ + s0)*HD;
        float* dst = p ? sQ1 : sQ0;
        #pragma unroll
        for (int i = 0; i < 4; i++) {
            int e4 = tid + i*256;
            int r = e4 >> 4, c = (e4 & 15) << 2;
            cpa16(smem_u32(&dst[r*PA + c]), Qb + r*HD + c);
        }
        if (tid < 16) cpa16(smem_u32(&smk[p][tid*4]), mask + (size_t)b*SEQ + s0 + tid*4);
        cp_commit();
    }

    for (int e4 = tid; e4 < NL*HD/4; e4 += 256) {
        int r = e4 >> 4, c = (e4 & 15) << 2;
        float4 kl = *(const float4*)&g_Kl[(size_t)bh*NL*HD + r*HD + c];
        float4 w  = *(const float4*)&g_W[(size_t)bh*NL*HD + r*HD + c];
        *(float4*)&sKl[r*PA + c] = make_float4(tf32r(kl.x), tf32r(kl.y), tf32r(kl.z), tf32r(kl.w));
        *(float4*)&sW[r*PB + c]  = make_float4(tf32r(w.x), tf32r(w.y), tf32r(w.z), tf32r(w.w));
    }

    for (int tt = 0; tt < NTF; tt++) {
        int buf = tt & 1;
        float* sQ = buf ? sQ1 : sQ0;     // raw Q tile; becomes P after pair barrier
        cp_wait<1>();
        __syncthreads();                  // Q tile ready (+ sKl/sW on tt=0)

        // pull this band's Q fragments (RNA-rounded) into regs, then free the band for P
        uint32_t qa[8][4];
        #pragma unroll
        for (int ks = 0; ks < 8; ks++) {
            int kb = ks*8 + t4;
            qa[ks][0] = tf32u(sQ[r0*PA + kb]);
            qa[ks][1] = tf32u(sQ[r1*PA + kb]);
            qa[ks][2] = tf32u(sQ[r0*PA + kb + 4]);
            qa[ks][3] = tf32u(sQ[r1*PA + kb + 4]);
        }
        bar_pair(wr + 1);                 // pair done reading its Q band

        float f0 = smk[buf][r0] * SCALE;
        float f1 = smk[buf][r1] * SCALE;
        float dp0 = 0.f, dp1 = 0.f;
        #pragma unroll
        for (int nt = 0; nt < 4; nt++) {
            float cf[4] = {0.f, 0.f, 0.f, 0.f};
            int n = wc*32 + nt*8 + g;
            #pragma unroll
            for (int ks = 0; ks < 8; ks++) {
                int kb = ks*8 + t4;
                uint32_t b0 = __float_as_uint(sKl[n*PA + kb]);
                uint32_t b1 = __float_as_uint(sKl[n*PA + kb + 4]);
                mma8(cf, qa[ks][0], qa[ks][1], qa[ks][2], qa[ks][3], b0, b1);
            }
            int cb = wc*32 + nt*8 + t4*2;
            float e0 = __expf(cf[0]*f0), e1 = __expf(cf[1]*f0);
            float e2 = __expf(cf[2]*f1), e3 = __expf(cf[3]*f1);
            dp0 += e0 + e1; dp1 += e2 + e3;
            *(float2*)&sQ[r0*PA + cb] = make_float2(tf32r(e0), tf32r(e1));
            *(float2*)&sQ[r1*PA + cb] = make_float2(tf32r(e2), tf32r(e3));
        }
        dp0 += __shfl_xor_sync(0xffffffffu, dp0, 1);
        dp0 += __shfl_xor_sync(0xffffffffu, dp0, 2);
        dp1 += __shfl_xor_sync(0xffffffffu, dp1, 1);
        dp1 += __shfl_xor_sync(0xffffffffu, dp1, 2);
        if (t4 == 0) { rsum[r0][wc] = dp0; rsum[r1][wc] = dp1; }
        bar_pair(wr + 1);                 // pair: P band + rsum visible

        float o[4][4];
        #pragma unroll
        for (int nt = 0; nt < 4; nt++)
            #pragma unroll
            for (int j = 0; j < 4; j++) o[nt][j] = 0.f;
        #pragma unroll
        for (int ks = 0; ks < 8; ks++) {
            int kb = ks*8 + t4;
            uint32_t a0 = __float_as_uint(sQ[r0*PA + kb]);
            uint32_t a1 = __float_as_uint(sQ[r1*PA + kb]);
            uint32_t a2 = __float_as_uint(sQ[r0*PA + kb + 4]);
            uint32_t a3 = __float_as_uint(sQ[r1*PA + kb + 4]);
            #pragma unroll
            for (int nt = 0; nt < 4; nt++) {
                int n = wc*32 + nt*8 + g;
                uint32_t b0 = __float_as_uint(sW[kb*PB + n]);
                uint32_t b1 = __float_as_uint(sW[(kb+4)*PB + n]);
                mma8(o[nt], a0, a1, a2, a3, b0, b1);
            }
        }
        int s0 = (blockIdx.x*NTF + tt)*TS;
        float ri0 = 1.f / (rsum[r0][0] + rsum[r0][1]);
        float ri1 = 1.f / (rsum[r1][0] + rsum[r1][1]);
        #pragma unroll
        for (int nt = 0; nt < 4; nt++) {
            int cb = wc*32 + nt*8 + t4*2;
            *(float2*)&out[((size_t)bh*SEQ + s0 + r0)*HD + cb] =
                make_float2(o[nt][0]*ri0, o[nt][1]*ri0);
            *(float2*)&out[((size_t)bh*SEQ + s0 + r1)*HD + cb] =
                make_float2(o[nt][2]*ri1, o[nt][3]*ri1);
        }
        __syncthreads();                  // all bands' P reads done before overwrite
        if (tt + 2 < NTF) {
            int sn = (blockIdx.x*NTF + tt + 2)*TS;
            const float* Qb = Q + ((size_t)bh*SEQ + sn)*HD;
            #pragma unroll
            for (int i = 0; i < 4; i++) {
                int e4 = tid + i*256;
                int r = e4 >> 4, c = (e4 & 15) << 2;
                cpa16(smem_u32(&sQ[r*PA + c]), Qb + r*HD + c);
            }
            if (tid < 16) cpa16(smem_u32(&smk[buf][tid*4]),
                                mask + (size_t)b*SEQ + sn + tid*4);
            cp_commit();
        }
    }
}

// ================= launch =================
extern "C" void kernel_launch(void* const* d_in, const int* in_sizes, int n_in,
                              void* d_out, int out_size) {
    const float* Q    = (const float*)d_in[0];
    const float* K    = (const float*)d_in[1];
    const float* V    = (const float*)d_in[2];
    const float* mask = (const float*)d_in[3];
    float* out = (float*)d_out;

    const int SMEM_MID = (3 * NL * PA + 2 * NL * PB) * sizeof(float);  // 89088
    const int SMEM_FIN = (3 * NL * PA + NL * PB) * sizeof(float);      // 70656
    cudaFuncSetAttribute(k_mid,   cudaFuncAttributeMaxDynamicSharedMemorySize, SMEM_MID);
    cudaFuncSetAttribute(k_final, cudaFuncAttributeMaxDynamicSharedMemorySize, SMEM_FIN);

    k_landmarks<<<dim3(NL, BH), 256>>>(Q, K, mask);     // launch 0
    k_kernel2<<<BH, NL>>>();                            // launch 1
    k_dummy<<<1, 32>>>();                               // launch 2 (slot shim)
    k_mid<<<dim3(NSPLIT + 1, BH), 256, SMEM_MID>>>(K, V, mask);  // launch 3 <- profiled
    k_mergewmat<<<BH, 256>>>();                         // launch 4
    k_final<<<dim3(SEQ/TS/NTF, BH), 256, SMEM_FIN>>>(Q, mask, out);  // launch 5
}